// round 15
// baseline (speedup 1.0000x reference)
#include <cuda_runtime.h>
#include <math.h>
#include <stdint.h>

#define NNODE 8192
#define DDIM  256
#define NPG   256
#define BGRP  32
#define NEDGE 131072
#define NMASK (BGRP * NPG)
#define ZERO_EPS 1e-8f
#define PLANE_H (NNODE * DDIM)

// ---------------- scratch ----------------------------------------------------
__device__ float g_H0[NNODE * DDIM];
__device__ float g_H1[NNODE * DDIM];
__device__ float g_G[3 * NNODE * DDIM];
__device__ float g_P[3 * NNODE * DDIM];
__device__ float g_HT[NNODE * DDIM];
__device__ float g_Ablk[BGRP * NPG * NPG];
__device__ float g_Adj[3 * BGRP * NPG * NPG];
__device__ float g_nrm[NNODE];
__device__ float g_rinv[NNODE];
__device__ float g_sc[NNODE];
__device__ float g_svec[DDIM];
__device__ float g_emf[NMASK];
__device__ float g_pmf[NMASK];
__device__ int   g_mask_mode;

// ---------------- tf32 helpers ----------------------------------------------
__device__ __forceinline__ float tf32_rna(float x) {
    uint32_t u;
    asm("cvt.rna.tf32.f32 %0, %1;" : "=r"(u) : "f"(x));
    return __uint_as_float(u);
}

__device__ __forceinline__ void mma8(float c[4], const float a[4], float b0, float b1) {
    asm volatile("mma.sync.aligned.m16n8k8.row.col.f32.tf32.tf32.f32 "
        "{%0,%1,%2,%3}, {%4,%5,%6,%7}, {%8,%9}, {%0,%1,%2,%3};"
        : "+f"(c[0]), "+f"(c[1]), "+f"(c[2]), "+f"(c[3])
        : "r"(__float_as_uint(a[0])), "r"(__float_as_uint(a[1])),
          "r"(__float_as_uint(a[2])), "r"(__float_as_uint(a[3])),
          "r"(__float_as_uint(b0)),  "r"(__float_as_uint(b1)));
}

__device__ __forceinline__ void cp_async16(float* smem_dst, const float* gsrc) {
    uint32_t d = (uint32_t)__cvta_generic_to_shared(smem_dst);
    asm volatile("cp.async.ca.shared.global [%0], [%1], 16;" :: "r"(d), "l"(gsrc));
}
#define CP_COMMIT() asm volatile("cp.async.commit_group;" ::: "memory")
#define CP_WAIT0()  asm volatile("cp.async.wait_group 0;" ::: "memory")

// ---------------- 128x64xK(=256) 3xTF32 mainloop, cp.async double-buffered ---
// Block = 256 thr = 8 warps in 4(M)x2(N); warp tile 32x32; mma m16n8k8.
// A row-major MxK (Ag at tile row 0), lda.
// NT=false: B row-major KxN (Bg at tile col 0), ldb.  NT=true: B NxK -> A@B^T.
// smem raw fp32 per buffer: sA [128][20] (2560) + sB (NT 64x20=1280 / NN 16x72).
#define AIDX(r,k) ((r)*20 + (k))
#define BNNI(k,n) ((k)*72 + (n))
#define BNTI(n,k) ((n)*20 + (k))
#define BUF_STRIDE 3840

template<bool NT>
__device__ __forceinline__ void mma_loop(const float* __restrict__ Ag, int lda,
                                         const float* __restrict__ Bg, int ldb,
                                         float* __restrict__ smem,
                                         float (*acc)[4][4])
{
    const int tid  = threadIdx.x;
    const int lane = tid & 31;
    const int warp = tid >> 5;
    const int gid  = lane >> 2, tig = lane & 3;
    const int wm   = (warp & 3) * 32, wn = (warp >> 2) * 32;
    const int ar   = tid >> 2, akq = (tid & 3) << 2;   // A rows / NT-B rows
    const int bk   = tid >> 4, bn4 = (tid & 15) << 2;  // NN-B loader

    // ---- stage-0 loads ----
    {
        float* sA = smem;
        float* sB = smem + 2560;
        cp_async16(&sA[AIDX(ar, akq)],      Ag + (size_t)ar * lda + akq);
        cp_async16(&sA[AIDX(ar + 64, akq)], Ag + (size_t)(ar + 64) * lda + akq);
        if (NT) cp_async16(&sB[BNTI(ar, akq)], Bg + (size_t)ar * ldb + akq);
        else    cp_async16(&sB[BNNI(bk, bn4)], Bg + (size_t)bk * ldb + bn4);
        CP_COMMIT();
    }

    for (int s = 0; s < 16; s++) {
        CP_WAIT0();
        __syncthreads();
        if (s + 1 < 16) {
            const int s1 = (s + 1) * 16;
            float* sA = smem + ((s + 1) & 1) * BUF_STRIDE;
            float* sB = sA + 2560;
            cp_async16(&sA[AIDX(ar, akq)],      Ag + (size_t)ar * lda + s1 + akq);
            cp_async16(&sA[AIDX(ar + 64, akq)], Ag + (size_t)(ar + 64) * lda + s1 + akq);
            if (NT) cp_async16(&sB[BNTI(ar, akq)], Bg + (size_t)ar * ldb + s1 + akq);
            else    cp_async16(&sB[BNNI(bk, bn4)], Bg + (size_t)(s1 + bk) * ldb + bn4);
            CP_COMMIT();
        }
        const float* sA = smem + (s & 1) * BUF_STRIDE;
        const float* sB = sA + 2560;
        #pragma unroll
        for (int kg = 0; kg < 2; kg++) {
            const int k0 = kg * 8 + tig;
            float ah[2][4], al[2][4];
            #pragma unroll
            for (int mt = 0; mt < 2; mt++) {
                const int r0 = wm + mt * 16 + gid;
                float raw[4];
                raw[0] = sA[AIDX(r0,     k0)];
                raw[1] = sA[AIDX(r0 + 8, k0)];
                raw[2] = sA[AIDX(r0,     k0 + 4)];
                raw[3] = sA[AIDX(r0 + 8, k0 + 4)];
                #pragma unroll
                for (int q = 0; q < 4; q++) {
                    float hi = tf32_rna(raw[q]);
                    ah[mt][q] = hi;
                    al[mt][q] = tf32_rna(raw[q] - hi);
                }
            }
            #pragma unroll
            for (int nt = 0; nt < 4; nt++) {
                const int cn = wn + nt * 8 + gid;
                float rb0, rb1;
                if (NT) {
                    rb0 = sB[BNTI(cn, k0)];
                    rb1 = sB[BNTI(cn, k0 + 4)];
                } else {
                    rb0 = sB[BNNI(k0,     cn)];
                    rb1 = sB[BNNI(k0 + 4, cn)];
                }
                float bh0 = tf32_rna(rb0);
                float bl0 = tf32_rna(rb0 - bh0);
                float bh1 = tf32_rna(rb1);
                float bl1 = tf32_rna(rb1 - bh1);
                #pragma unroll
                for (int mt = 0; mt < 2; mt++) {
                    mma8(acc[mt][nt], ah[mt], bh0, bh1);
                    mma8(acc[mt][nt], al[mt], bh0, bh1);
                    mma8(acc[mt][nt], ah[mt], bl0, bl1);
                }
            }
        }
    }
    __syncthreads();
}

#define SMEM_FLOATS 7680   // 30KB (2 buffers x 15KB)

// ---------------- GEMM kernels (tile 128x64) ---------------------------------
__global__ __launch_bounds__(256, 2) void k_gemm_nn(const float* __restrict__ A,
                                                    const float* __restrict__ W,
                                                    float* __restrict__ C) {
    __shared__ __align__(16) float sm[SMEM_FLOATS];
    const int m0 = blockIdx.y * 128, n0 = blockIdx.x * 64, z = blockIdx.z;
    float acc[2][4][4];
    #pragma unroll
    for (int i = 0; i < 2; i++)
        #pragma unroll
        for (int j = 0; j < 4; j++)
            #pragma unroll
            for (int q = 0; q < 4; q++) acc[i][j][q] = 0.f;
    mma_loop<false>(A + (size_t)m0 * DDIM, DDIM,
                    W + (size_t)z * DDIM * DDIM + n0, DDIM, sm, acc);
    float* Cg = C + (size_t)z * NNODE * DDIM;
    const int lane = threadIdx.x & 31, warp = threadIdx.x >> 5;
    const int gid = lane >> 2, tig = lane & 3;
    const int wm = (warp & 3) * 32, wn = (warp >> 2) * 32;
    #pragma unroll
    for (int mt = 0; mt < 2; mt++)
        #pragma unroll
        for (int nt = 0; nt < 4; nt++) {
            int r = m0 + wm + mt * 16 + gid;
            int c = n0 + wn + nt * 8 + 2 * tig;
            *(float2*)&Cg[(size_t)r * DDIM + c] = make_float2(acc[mt][nt][0], acc[mt][nt][1]);
            *(float2*)&Cg[(size_t)(r + 8) * DDIM + c] = make_float2(acc[mt][nt][2], acc[mt][nt][3]);
        }
}

__global__ __launch_bounds__(256, 2) void k_corr(const float* __restrict__ x,
                                                 const float* __restrict__ sc,
                                                 float* __restrict__ Ablk) {
    __shared__ __align__(16) float sm[SMEM_FLOATS];
    const int m0 = blockIdx.y * 128, n0 = blockIdx.x * 64, b = blockIdx.z;
    const float* base = x + (size_t)b * NPG * DDIM;
    float acc[2][4][4];
    #pragma unroll
    for (int i = 0; i < 2; i++)
        #pragma unroll
        for (int j = 0; j < 4; j++)
            #pragma unroll
            for (int q = 0; q < 4; q++) acc[i][j][q] = 0.f;
    mma_loop<true>(base + (size_t)m0 * DDIM, DDIM,
                   base + (size_t)n0 * DDIM, DDIM, sm, acc);
    const int lane = threadIdx.x & 31, warp = threadIdx.x >> 5;
    const int gid = lane >> 2, tig = lane & 3;
    const int wm = (warp & 3) * 32, wn = (warp >> 2) * 32;
    const float* scb = sc + b * NPG;
    #pragma unroll
    for (int mt = 0; mt < 2; mt++)
        #pragma unroll
        for (int nt = 0; nt < 4; nt++) {
            int li = m0 + wm + mt * 16 + gid;
            int lj = n0 + wn + nt * 8 + 2 * tig;
            float s0 = scb[li], s1 = scb[li + 8];
            float c0 = scb[lj], c1 = scb[lj + 1];
            float* row0 = Ablk + ((size_t)b * NPG + li) * NPG;
            float* row1 = Ablk + ((size_t)b * NPG + li + 8) * NPG;
            *(float2*)&row0[lj] = make_float2(acc[mt][nt][0] * s0 * c0, acc[mt][nt][1] * s0 * c1);
            *(float2*)&row1[lj] = make_float2(acc[mt][nt][2] * s1 * c0, acc[mt][nt][3] * s1 * c1);
        }
}

__global__ __launch_bounds__(256, 2) void k_aggr_part(const float* __restrict__ Adj,
                                                      const float* __restrict__ G,
                                                      float* __restrict__ P) {
    __shared__ __align__(16) float sm[SMEM_FLOATS];
    const int m0 = blockIdx.y * 128, n0 = blockIdx.x * 64;
    const int z = blockIdx.z, b = z & 31, t = z >> 5;
    float acc[2][4][4];
    #pragma unroll
    for (int i = 0; i < 2; i++)
        #pragma unroll
        for (int j = 0; j < 4; j++)
            #pragma unroll
            for (int q = 0; q < 4; q++) acc[i][j][q] = 0.f;
    const float* Ag = Adj + ((size_t)(t * BGRP + b)) * NPG * NPG + (size_t)m0 * NPG;
    const float* Bg = G + (size_t)t * PLANE_H + (size_t)b * NPG * DDIM + n0;
    mma_loop<false>(Ag, NPG, Bg, DDIM, sm, acc);
    float* Pp = P + (size_t)t * PLANE_H + (size_t)b * NPG * DDIM;
    const int lane = threadIdx.x & 31, warp = threadIdx.x >> 5;
    const int gid = lane >> 2, tig = lane & 3;
    const int wm = (warp & 3) * 32, wn = (warp >> 2) * 32;
    #pragma unroll
    for (int mt = 0; mt < 2; mt++)
        #pragma unroll
        for (int nt = 0; nt < 4; nt++) {
            int r = m0 + wm + mt * 16 + gid;
            int c = n0 + wn + nt * 8 + 2 * tig;
            *(float2*)&Pp[(size_t)r * DDIM + c] = make_float2(acc[mt][nt][0], acc[mt][nt][1]);
            *(float2*)&Pp[(size_t)(r + 8) * DDIM + c] = make_float2(acc[mt][nt][2], acc[mt][nt][3]);
        }
}

__global__ void k_red(const float* __restrict__ P, const float* __restrict__ bgl,
                      float* __restrict__ H) {
    int i = blockIdx.x * blockDim.x + threadIdx.x;
    if (i >= PLANE_H) return;
    int c = i & 255;
    float bias = bgl[c] + bgl[DDIM + c] + bgl[2 * DDIM + c];
    float v = P[i] + P[i + PLANE_H] + P[i + 2 * PLANE_H] + bias;
    H[i] = fmaxf(v, 0.f);
}

__global__ __launch_bounds__(256, 2) void k_ahat(const float* __restrict__ HT,
                                                 const float* __restrict__ Hn,
                                                 float* __restrict__ Ablk) {
    __shared__ __align__(16) float sm[SMEM_FLOATS];
    const int m0 = blockIdx.y * 128, n0 = blockIdx.x * 64, b = blockIdx.z;
    float acc[2][4][4];
    #pragma unroll
    for (int i = 0; i < 2; i++)
        #pragma unroll
        for (int j = 0; j < 4; j++)
            #pragma unroll
            for (int q = 0; q < 4; q++) acc[i][j][q] = 0.f;
    mma_loop<true>(HT + ((size_t)b * NPG + m0) * DDIM, DDIM,
                   Hn + ((size_t)b * NPG + n0) * DDIM, DDIM, sm, acc);
    const int lane = threadIdx.x & 31, warp = threadIdx.x >> 5;
    const int gid = lane >> 2, tig = lane & 3;
    const int wm = (warp & 3) * 32, wn = (warp >> 2) * 32;
    #pragma unroll
    for (int mt = 0; mt < 2; mt++)
        #pragma unroll
        for (int nt = 0; nt < 4; nt++) {
            int li = m0 + wm + mt * 16 + gid;
            int lj = n0 + wn + nt * 8 + 2 * tig;
            float* row0 = Ablk + ((size_t)b * NPG + li) * NPG;
            float* row1 = Ablk + ((size_t)b * NPG + li + 8) * NPG;
            float2 o0 = *(const float2*)&row0[lj];
            float2 o1 = *(const float2*)&row1[lj];
            float2 v0, v1;
            v0.x = 0.5f * o0.x + 0.5f / (1.0f + expf(-acc[mt][nt][0]));
            v0.y = 0.5f * o0.y + 0.5f / (1.0f + expf(-acc[mt][nt][1]));
            v1.x = 0.5f * o1.x + 0.5f / (1.0f + expf(-acc[mt][nt][2]));
            v1.y = 0.5f * o1.y + 0.5f / (1.0f + expf(-acc[mt][nt][3]));
            *(float2*)&row0[lj] = v0;
            *(float2*)&row1[lj] = v1;
        }
}

// ---------------- small kernels ---------------------------------------------
__global__ void k_mask_detect(const unsigned char* __restrict__ em,
                              const unsigned char* __restrict__ pm) {
    __shared__ int nz[4];
    if (threadIdx.x < 4) nz[threadIdx.x] = 0;
    __syncthreads();
    int loc[4] = {0, 0, 0, 0};
    for (int i = threadIdx.x; i < NMASK; i += 256) {
        if (em[i]) loc[i & 3]++;
        if (pm[i]) loc[i & 3]++;
    }
    #pragma unroll
    for (int j = 0; j < 4; j++) if (loc[j]) atomicAdd(&nz[j], loc[j]);
    __syncthreads();
    if (threadIdx.x == 0) {
        int mode;
        if (nz[1] > 0) mode = 0;
        else if (nz[0] > 0) mode = 1;
        else mode = 2;
        g_mask_mode = mode;
    }
}

__global__ void k_mask_decode(const unsigned char* __restrict__ em,
                              const unsigned char* __restrict__ pm,
                              float* __restrict__ emf, float* __restrict__ pmf) {
    int i = blockIdx.x * blockDim.x + threadIdx.x;
    if (i >= NMASK) return;
    int mode = g_mask_mode;
    float e, p;
    if (mode == 0) { e = em[i] ? 1.f : 0.f; p = pm[i] ? 1.f : 0.f; }
    else if (mode == 1) { e = ((const int*)em)[i] ? 1.f : 0.f; p = ((const int*)pm)[i] ? 1.f : 0.f; }
    else { e = (((const float*)em)[i] != 0.f) ? 1.f : 0.f; p = (((const float*)pm)[i] != 0.f) ? 1.f : 0.f; }
    emf[i] = e; pmf[i] = p;
}

__global__ void k_rownorm(const float* __restrict__ x, float* __restrict__ nrm,
                          float* __restrict__ rinv) {
    int warp = (blockIdx.x * blockDim.x + threadIdx.x) >> 5;
    int lane = threadIdx.x & 31;
    if (warp >= NNODE) return;
    const float* r = x + (size_t)warp * DDIM;
    float s = 0.f;
    for (int j = lane; j < DDIM; j += 32) { float v = r[j]; s += v * v; }
    #pragma unroll
    for (int o = 16; o; o >>= 1) s += __shfl_xor_sync(0xffffffffu, s, o);
    if (!lane) { float n = sqrtf(s); nrm[warp] = n; rinv[warp] = 1.0f / n; }
}

__global__ void k_colsum(const float* __restrict__ x, const float* __restrict__ rinv,
                         float* __restrict__ svec) {
    int d = threadIdx.x;
    int r0 = blockIdx.x * 32;
    float acc = 0.f;
    for (int r = r0; r < r0 + 32; r++)
        acc += x[(size_t)r * DDIM + d] * rinv[r];
    atomicAdd(&svec[d], acc);
}

__global__ void k_scale(const float* __restrict__ x, const float* __restrict__ rinv,
                        const float* __restrict__ svec, float* __restrict__ sc) {
    int warp = (blockIdx.x * blockDim.x + threadIdx.x) >> 5;
    int lane = threadIdx.x & 31;
    if (warp >= NNODE) return;
    const float* r = x + (size_t)warp * DDIM;
    float dot = 0.f;
    for (int j = lane; j < DDIM; j += 32) dot += r[j] * svec[j];
    #pragma unroll
    for (int o = 16; o; o >>= 1) dot += __shfl_xor_sync(0xffffffffu, dot, o);
    if (!lane) {
        float rowsum = dot * rinv[warp];
        sc[warp] = rsqrtf(fabsf(rowsum) + ZERO_EPS) * rinv[warp];
    }
}

__global__ void k_scatter_w(const int* __restrict__ ei, const float* __restrict__ ew,
                            float* __restrict__ Adj) {
    int e = blockIdx.x * blockDim.x + threadIdx.x;
    if (e >= NEDGE) return;
    int src = ei[e], dst = ei[NEDGE + e];
    int b = src >> 8, sl = src & 255, dl = dst & 255;
    atomicAdd(&Adj[(((size_t)b << 8) + dl) * NPG + sl], ew[e]);
}

__global__ void k_scatter_A(const int* __restrict__ ei, const float* __restrict__ Ablk,
                            float* __restrict__ Adj) {
    int e = blockIdx.x * blockDim.x + threadIdx.x;
    if (e >= NEDGE) return;
    int src = ei[e], dst = ei[NEDGE + e];
    int b = src >> 8, sl = src & 255, dl = dst & 255;
    float w = Ablk[(((size_t)b << 8) + sl) * NPG + dl];
    atomicAdd(&Adj[(((size_t)b << 8) + dl) * NPG + sl], w);
}

// ---------------- final maps ------------------------------------------------
__global__ __launch_bounds__(256) void k_final(const float* __restrict__ Ablk,
                                               const float* __restrict__ emf,
                                               const float* __restrict__ pmf,
                                               float* __restrict__ out) {
    int b = blockIdx.x;
    __shared__ float ems[NPG], pms[NPG];
    __shared__ float me[NPG], mp[NPG];
    __shared__ float red[256];
    int t = threadIdx.x;
    ems[t] = emf[b * NPG + t];
    pms[t] = pmf[b * NPG + t];
    __syncthreads();
    int warp = t >> 5, lane = t & 31;
    for (int r = warp; r < NPG; r += 8) {
        const float* row = Ablk + ((size_t)b * NPG + r) * NPG;
        float s = 0.f, es = 0.f, ps = 0.f;
        for (int j = lane; j < NPG; j += 32) {
            float a = row[j];
            s += a; es += a * ems[j]; ps += a * pms[j];
        }
        #pragma unroll
        for (int o = 16; o; o >>= 1) {
            s  += __shfl_xor_sync(0xffffffffu, s, o);
            es += __shfl_xor_sync(0xffffffffu, es, o);
            ps += __shfl_xor_sync(0xffffffffu, ps, o);
        }
        if (!lane) { me[r] = s - ps; mp[r] = s - es; }
    }
    __syncthreads();
    for (int pass = 0; pass < 2; pass++) {
        float v = pass ? mp[t] : me[t];
        red[t] = v; __syncthreads();
        for (int s2 = 128; s2; s2 >>= 1) {
            if (t < s2) red[t] = fminf(red[t], red[t + s2]);
            __syncthreads();
        }
        float mn = red[0]; __syncthreads();
        red[t] = v; __syncthreads();
        for (int s2 = 128; s2; s2 >>= 1) {
            if (t < s2) red[t] = fmaxf(red[t], red[t + s2]);
            __syncthreads();
        }
        float mx = red[0]; __syncthreads();
        float u = (v - mn) / (mx - mn + ZERO_EPS);
        red[t] = u; __syncthreads();
        for (int s2 = 128; s2; s2 >>= 1) {
            if (t < s2) red[t] += red[t + s2];
            __syncthreads();
        }
        float sm = red[0]; __syncthreads();
        out[pass * (BGRP * NPG) + b * NPG + t] = u / (sm + ZERO_EPS);
    }
}

// ---------------- host ------------------------------------------------------
extern "C" void kernel_launch(void* const* d_in, const int* in_sizes, int n_in,
                              void* d_out, int out_size) {
    const float*     x    = (const float*)d_in[0];
    const int*       ei_e = (const int*)d_in[1];
    const float*     ew_e = (const float*)d_in[2];
    const int*       ei_p = (const int*)d_in[3];
    const float*     ew_p = (const float*)d_in[4];
    const int*       ei_o = (const int*)d_in[5];
    const float*     ew_o = (const float*)d_in[6];
    const unsigned char* em = (const unsigned char*)d_in[7];
    const unsigned char* pm = (const unsigned char*)d_in[8];
    const float*     Wg   = (const float*)d_in[9];
    const float*     bg   = (const float*)d_in[10];
    const float*     Td   = (const float*)d_in[11];
    float* out = (float*)d_out;

    float *H0, *H1, *G, *P, *HT, *Ablk, *Adj, *nrm, *rinv, *sc, *svec, *emf, *pmf;
    cudaGetSymbolAddress((void**)&H0,   g_H0);
    cudaGetSymbolAddress((void**)&H1,   g_H1);
    cudaGetSymbolAddress((void**)&G,    g_G);
    cudaGetSymbolAddress((void**)&P,    g_P);
    cudaGetSymbolAddress((void**)&HT,   g_HT);
    cudaGetSymbolAddress((void**)&Ablk, g_Ablk);
    cudaGetSymbolAddress((void**)&Adj,  g_Adj);
    cudaGetSymbolAddress((void**)&nrm,  g_nrm);
    cudaGetSymbolAddress((void**)&rinv, g_rinv);
    cudaGetSymbolAddress((void**)&sc,   g_sc);
    cudaGetSymbolAddress((void**)&svec, g_svec);
    cudaGetSymbolAddress((void**)&emf,  g_emf);
    cudaGetSymbolAddress((void**)&pmf,  g_pmf);

    static cudaStream_t s1 = nullptr;
    static cudaEvent_t evR, evAdj, evCorr, evH0, evG1;
    if (!s1) {
        cudaStreamCreateWithFlags(&s1, cudaStreamNonBlocking);
        cudaEventCreateWithFlags(&evR,    cudaEventDisableTiming);
        cudaEventCreateWithFlags(&evAdj,  cudaEventDisableTiming);
        cudaEventCreateWithFlags(&evCorr, cudaEventDisableTiming);
        cudaEventCreateWithFlags(&evH0,   cudaEventDisableTiming);
        cudaEventCreateWithFlags(&evG1,   cudaEventDisableTiming);
    }

    const size_t ADJ1 = (size_t)BGRP * NPG * NPG;

    // ---- fork side stream ----
    cudaEventRecord(evR, 0);
    cudaStreamWaitEvent(s1, evR, 0);

    // ---- side stream: masks, normalization chain, L0 adjacency, corr ----
    k_mask_detect<<<1, 256, 0, s1>>>(em, pm);
    k_mask_decode<<<NMASK / 256, 256, 0, s1>>>(em, pm, emf, pmf);
    cudaMemsetAsync(svec, 0, DDIM * sizeof(float), s1);
    k_rownorm<<<NNODE / 8, 256, 0, s1>>>(x, nrm, rinv);
    k_colsum<<<256, 256, 0, s1>>>(x, rinv, svec);
    k_scale<<<NNODE / 8, 256, 0, s1>>>(x, rinv, svec, sc);
    cudaMemsetAsync(Adj, 0, 3 * ADJ1 * sizeof(float), s1);
    k_scatter_w<<<NEDGE / 256, 256, 0, s1>>>(ei_e, ew_e, Adj);
    k_scatter_w<<<NEDGE / 256, 256, 0, s1>>>(ei_p, ew_p, Adj + ADJ1);
    k_scatter_w<<<NEDGE / 256, 256, 0, s1>>>(ei_o, ew_o, Adj + 2 * ADJ1);
    cudaEventRecord(evAdj, s1);
    k_corr<<<dim3(4, 2, BGRP), 256, 0, s1>>>(x, sc, Ablk);
    cudaEventRecord(evCorr, s1);

    // ---- main: layer-0 feature GEMM ----
    k_gemm_nn<<<dim3(4, 64, 3), 256>>>(x, Wg, G);
    cudaStreamWaitEvent(0, evAdj, 0);
    k_aggr_part<<<dim3(4, 2, 96), 256>>>(Adj, G, P);
    k_red<<<PLANE_H / 256, 256>>>(P, bg, H0);
    cudaEventRecord(evH0, 0);

    // ---- side stream: layer-1 feature GEMM overlapped with L0 epilogue ----
    cudaStreamWaitEvent(s1, evH0, 0);
    k_gemm_nn<<<dim3(4, 64, 3), 256, 0, s1>>>(H0, Wg + 3 * DDIM * DDIM, G);
    cudaEventRecord(evG1, s1);

    // ---- main: HT, ahat L0, layer-1 adjacency ----
    k_gemm_nn<<<dim3(4, 64, 1), 256>>>(H0, Td, HT);
    cudaStreamWaitEvent(0, evCorr, 0);
    k_ahat<<<dim3(4, 2, BGRP), 256>>>(HT, H0, Ablk);
    cudaMemsetAsync(Adj, 0, 3 * ADJ1 * sizeof(float));
    k_scatter_A<<<NEDGE / 256, 256>>>(ei_e, Ablk, Adj);
    k_scatter_A<<<NEDGE / 256, 256>>>(ei_p, Ablk, Adj + ADJ1);
    k_scatter_A<<<NEDGE / 256, 256>>>(ei_o, Ablk, Adj + 2 * ADJ1);

    // ---- main: layer 1 (join side stream's G) ----
    cudaStreamWaitEvent(0, evG1, 0);
    k_aggr_part<<<dim3(4, 2, 96), 256>>>(Adj, G, P);
    k_red<<<PLANE_H / 256, 256>>>(P, bg + 3 * DDIM, H1);
    k_gemm_nn<<<dim3(4, 64, 1), 256>>>(H1, Td + DDIM * DDIM, HT);
    k_ahat<<<dim3(4, 2, BGRP), 256>>>(HT, H1, Ablk);

    // ---- final maps ----
    k_final<<<BGRP, 256>>>(Ablk, emf, pmf, out);
}

// round 16
// speedup vs baseline: 1.0617x; 1.0617x over previous
#include <cuda_runtime.h>
#include <math.h>
#include <stdint.h>

#define NNODE 8192
#define DDIM  256
#define NPG   256
#define BGRP  32
#define NEDGE 131072
#define NMASK (BGRP * NPG)
#define ZERO_EPS 1e-8f
#define PLANE_H (NNODE * DDIM)

// ---------------- scratch ----------------------------------------------------
__device__ float g_H0[NNODE * DDIM];
__device__ float g_H1[NNODE * DDIM];
__device__ float g_G[3 * NNODE * DDIM];
__device__ float g_P[3 * NNODE * DDIM];
__device__ float g_HT[NNODE * DDIM];
__device__ float g_Ablk[BGRP * NPG * NPG];
__device__ float g_Adj[3 * BGRP * NPG * NPG];
__device__ float g_nrm[NNODE];
__device__ float g_rinv[NNODE];
__device__ float g_sc[NNODE];
__device__ float g_svec[DDIM];
__device__ float g_emf[NMASK];
__device__ float g_pmf[NMASK];
__device__ int   g_mask_mode;

// ---------------- tf32 helpers ----------------------------------------------
__device__ __forceinline__ float tf32_rna(float x) {
    uint32_t u;
    asm("cvt.rna.tf32.f32 %0, %1;" : "=r"(u) : "f"(x));
    return __uint_as_float(u);
}

__device__ __forceinline__ void mma8(float c[4], const float a[4], float b0, float b1) {
    asm volatile("mma.sync.aligned.m16n8k8.row.col.f32.tf32.tf32.f32 "
        "{%0,%1,%2,%3}, {%4,%5,%6,%7}, {%8,%9}, {%0,%1,%2,%3};"
        : "+f"(c[0]), "+f"(c[1]), "+f"(c[2]), "+f"(c[3])
        : "r"(__float_as_uint(a[0])), "r"(__float_as_uint(a[1])),
          "r"(__float_as_uint(a[2])), "r"(__float_as_uint(a[3])),
          "r"(__float_as_uint(b0)),  "r"(__float_as_uint(b1)));
}

__device__ __forceinline__ void cp_async16(float* smem_dst, const float* gsrc) {
    uint32_t d = (uint32_t)__cvta_generic_to_shared(smem_dst);
    asm volatile("cp.async.ca.shared.global [%0], [%1], 16;" :: "r"(d), "l"(gsrc));
}
#define CP_COMMIT() asm volatile("cp.async.commit_group;" ::: "memory")
#define CP_WAIT0()  asm volatile("cp.async.wait_group 0;" ::: "memory")

#define AIDX(r,k) ((r)*20 + (k))

// ================= 128x128 tile mainloop (R13/R14-proven) ====================
#define BNNI(k,n) ((k)*136 + (n))
#define BNTI(n,k) ((n)*20 + (k))
#define BUF_STRIDE_128 5120

template<bool NT>
__device__ __forceinline__ void mma_loop128(const float* __restrict__ Ag, int lda,
                                            const float* __restrict__ Bg, int ldb,
                                            float* __restrict__ smem,
                                            float (*acc)[8][4])
{
    const int tid  = threadIdx.x;
    const int lane = tid & 31;
    const int warp = tid >> 5;
    const int gid  = lane >> 2, tig = lane & 3;
    const int wm   = (warp & 3) * 32, wn = (warp >> 2) * 64;
    const int ar   = tid >> 2, akq = (tid & 3) << 2;
    const int bk   = tid >> 5, bn4 = (tid & 31) << 2;

    {
        float* sA = smem;
        float* sB = smem + 2560;
        cp_async16(&sA[AIDX(ar, akq)],      Ag + (size_t)ar * lda + akq);
        cp_async16(&sA[AIDX(ar + 64, akq)], Ag + (size_t)(ar + 64) * lda + akq);
        if (NT) {
            cp_async16(&sB[BNTI(ar, akq)],      Bg + (size_t)ar * ldb + akq);
            cp_async16(&sB[BNTI(ar + 64, akq)], Bg + (size_t)(ar + 64) * ldb + akq);
        } else {
            cp_async16(&sB[BNNI(bk, bn4)],     Bg + (size_t)bk * ldb + bn4);
            cp_async16(&sB[BNNI(bk + 8, bn4)], Bg + (size_t)(bk + 8) * ldb + bn4);
        }
        CP_COMMIT();
    }

    for (int s = 0; s < 16; s++) {
        CP_WAIT0();
        __syncthreads();
        if (s + 1 < 16) {
            const int s1 = (s + 1) * 16;
            float* sA = smem + ((s + 1) & 1) * BUF_STRIDE_128;
            float* sB = sA + 2560;
            cp_async16(&sA[AIDX(ar, akq)],      Ag + (size_t)ar * lda + s1 + akq);
            cp_async16(&sA[AIDX(ar + 64, akq)], Ag + (size_t)(ar + 64) * lda + s1 + akq);
            if (NT) {
                cp_async16(&sB[BNTI(ar, akq)],      Bg + (size_t)ar * ldb + s1 + akq);
                cp_async16(&sB[BNTI(ar + 64, akq)], Bg + (size_t)(ar + 64) * ldb + s1 + akq);
            } else {
                cp_async16(&sB[BNNI(bk, bn4)],     Bg + (size_t)(s1 + bk) * ldb + bn4);
                cp_async16(&sB[BNNI(bk + 8, bn4)], Bg + (size_t)(s1 + bk + 8) * ldb + bn4);
            }
            CP_COMMIT();
        }
        const float* sA = smem + (s & 1) * BUF_STRIDE_128;
        const float* sB = sA + 2560;
        #pragma unroll
        for (int kg = 0; kg < 2; kg++) {
            const int k0 = kg * 8 + tig;
            float ah[2][4], al[2][4];
            #pragma unroll
            for (int mt = 0; mt < 2; mt++) {
                const int r0 = wm + mt * 16 + gid;
                float raw[4];
                raw[0] = sA[AIDX(r0,     k0)];
                raw[1] = sA[AIDX(r0 + 8, k0)];
                raw[2] = sA[AIDX(r0,     k0 + 4)];
                raw[3] = sA[AIDX(r0 + 8, k0 + 4)];
                #pragma unroll
                for (int q = 0; q < 4; q++) {
                    float hi = tf32_rna(raw[q]);
                    ah[mt][q] = hi;
                    al[mt][q] = tf32_rna(raw[q] - hi);
                }
            }
            #pragma unroll
            for (int nt = 0; nt < 8; nt++) {
                const int cn = wn + nt * 8 + gid;
                float rb0, rb1;
                if (NT) {
                    rb0 = sB[BNTI(cn, k0)];
                    rb1 = sB[BNTI(cn, k0 + 4)];
                } else {
                    rb0 = sB[BNNI(k0,     cn)];
                    rb1 = sB[BNNI(k0 + 4, cn)];
                }
                float bh0 = tf32_rna(rb0);
                float bl0 = tf32_rna(rb0 - bh0);
                float bh1 = tf32_rna(rb1);
                float bl1 = tf32_rna(rb1 - bh1);
                #pragma unroll
                for (int mt = 0; mt < 2; mt++) {
                    mma8(acc[mt][nt], ah[mt], bh0, bh1);
                    mma8(acc[mt][nt], al[mt], bh0, bh1);
                    mma8(acc[mt][nt], ah[mt], bl0, bl1);
                }
            }
        }
    }
    __syncthreads();
}

#define SMEM_FLOATS_128 10240  // 40KB

// ================= 128x64 tile mainloop (R15-proven) =========================
#define BNNI64(k,n) ((k)*72 + (n))
#define BUF_STRIDE_64 3840

template<bool NT>
__device__ __forceinline__ void mma_loop64(const float* __restrict__ Ag, int lda,
                                           const float* __restrict__ Bg, int ldb,
                                           float* __restrict__ smem,
                                           float (*acc)[4][4])
{
    const int tid  = threadIdx.x;
    const int lane = tid & 31;
    const int warp = tid >> 5;
    const int gid  = lane >> 2, tig = lane & 3;
    const int wm   = (warp & 3) * 32, wn = (warp >> 2) * 32;
    const int ar   = tid >> 2, akq = (tid & 3) << 2;
    const int bk   = tid >> 4, bn4 = (tid & 15) << 2;

    {
        float* sA = smem;
        float* sB = smem + 2560;
        cp_async16(&sA[AIDX(ar, akq)],      Ag + (size_t)ar * lda + akq);
        cp_async16(&sA[AIDX(ar + 64, akq)], Ag + (size_t)(ar + 64) * lda + akq);
        if (NT) cp_async16(&sB[BNTI(ar, akq)],   Bg + (size_t)ar * ldb + akq);
        else    cp_async16(&sB[BNNI64(bk, bn4)], Bg + (size_t)bk * ldb + bn4);
        CP_COMMIT();
    }

    for (int s = 0; s < 16; s++) {
        CP_WAIT0();
        __syncthreads();
        if (s + 1 < 16) {
            const int s1 = (s + 1) * 16;
            float* sA = smem + ((s + 1) & 1) * BUF_STRIDE_64;
            float* sB = sA + 2560;
            cp_async16(&sA[AIDX(ar, akq)],      Ag + (size_t)ar * lda + s1 + akq);
            cp_async16(&sA[AIDX(ar + 64, akq)], Ag + (size_t)(ar + 64) * lda + s1 + akq);
            if (NT) cp_async16(&sB[BNTI(ar, akq)],   Bg + (size_t)ar * ldb + s1 + akq);
            else    cp_async16(&sB[BNNI64(bk, bn4)], Bg + (size_t)(s1 + bk) * ldb + bn4);
            CP_COMMIT();
        }
        const float* sA = smem + (s & 1) * BUF_STRIDE_64;
        const float* sB = sA + 2560;
        #pragma unroll
        for (int kg = 0; kg < 2; kg++) {
            const int k0 = kg * 8 + tig;
            float ah[2][4], al[2][4];
            #pragma unroll
            for (int mt = 0; mt < 2; mt++) {
                const int r0 = wm + mt * 16 + gid;
                float raw[4];
                raw[0] = sA[AIDX(r0,     k0)];
                raw[1] = sA[AIDX(r0 + 8, k0)];
                raw[2] = sA[AIDX(r0,     k0 + 4)];
                raw[3] = sA[AIDX(r0 + 8, k0 + 4)];
                #pragma unroll
                for (int q = 0; q < 4; q++) {
                    float hi = tf32_rna(raw[q]);
                    ah[mt][q] = hi;
                    al[mt][q] = tf32_rna(raw[q] - hi);
                }
            }
            #pragma unroll
            for (int nt = 0; nt < 4; nt++) {
                const int cn = wn + nt * 8 + gid;
                float rb0, rb1;
                if (NT) {
                    rb0 = sB[BNTI(cn, k0)];
                    rb1 = sB[BNTI(cn, k0 + 4)];
                } else {
                    rb0 = sB[BNNI64(k0,     cn)];
                    rb1 = sB[BNNI64(k0 + 4, cn)];
                }
                float bh0 = tf32_rna(rb0);
                float bl0 = tf32_rna(rb0 - bh0);
                float bh1 = tf32_rna(rb1);
                float bl1 = tf32_rna(rb1 - bh1);
                #pragma unroll
                for (int mt = 0; mt < 2; mt++) {
                    mma8(acc[mt][nt], ah[mt], bh0, bh1);
                    mma8(acc[mt][nt], al[mt], bh0, bh1);
                    mma8(acc[mt][nt], ah[mt], bl0, bl1);
                }
            }
        }
    }
    __syncthreads();
}

#define SMEM_FLOATS_64 7680    // 30KB

// ---------------- GEMM kernels ----------------------------------------------
// big feature GEMM: 128x128 tiles, grid (2,64,3) = 384 blocks
__global__ __launch_bounds__(256, 2) void k_gemm_nn(const float* __restrict__ A,
                                                    const float* __restrict__ W,
                                                    float* __restrict__ C) {
    __shared__ __align__(16) float sm[SMEM_FLOATS_128];
    const int m0 = blockIdx.y * 128, n0 = blockIdx.x * 128, z = blockIdx.z;
    float acc[2][8][4];
    #pragma unroll
    for (int i = 0; i < 2; i++)
        #pragma unroll
        for (int j = 0; j < 8; j++)
            #pragma unroll
            for (int q = 0; q < 4; q++) acc[i][j][q] = 0.f;
    mma_loop128<false>(A + (size_t)m0 * DDIM, DDIM,
                       W + (size_t)z * DDIM * DDIM + n0, DDIM, sm, acc);
    float* Cg = C + (size_t)z * NNODE * DDIM;
    const int lane = threadIdx.x & 31, warp = threadIdx.x >> 5;
    const int gid = lane >> 2, tig = lane & 3;
    const int wm = (warp & 3) * 32, wn = (warp >> 2) * 64;
    #pragma unroll
    for (int mt = 0; mt < 2; mt++)
        #pragma unroll
        for (int nt = 0; nt < 8; nt++) {
            int r = m0 + wm + mt * 16 + gid;
            int c = n0 + wn + nt * 8 + 2 * tig;
            *(float2*)&Cg[(size_t)r * DDIM + c] = make_float2(acc[mt][nt][0], acc[mt][nt][1]);
            *(float2*)&Cg[(size_t)(r + 8) * DDIM + c] = make_float2(acc[mt][nt][2], acc[mt][nt][3]);
        }
}

// HT GEMM: 128x64 tiles, grid (4,64,1) = 256 blocks
__global__ __launch_bounds__(256, 2) void k_gemm_ht(const float* __restrict__ A,
                                                    const float* __restrict__ W,
                                                    float* __restrict__ C) {
    __shared__ __align__(16) float sm[SMEM_FLOATS_64];
    const int m0 = blockIdx.y * 128, n0 = blockIdx.x * 64;
    float acc[2][4][4];
    #pragma unroll
    for (int i = 0; i < 2; i++)
        #pragma unroll
        for (int j = 0; j < 4; j++)
            #pragma unroll
            for (int q = 0; q < 4; q++) acc[i][j][q] = 0.f;
    mma_loop64<false>(A + (size_t)m0 * DDIM, DDIM, W + n0, DDIM, sm, acc);
    const int lane = threadIdx.x & 31, warp = threadIdx.x >> 5;
    const int gid = lane >> 2, tig = lane & 3;
    const int wm = (warp & 3) * 32, wn = (warp >> 2) * 32;
    #pragma unroll
    for (int mt = 0; mt < 2; mt++)
        #pragma unroll
        for (int nt = 0; nt < 4; nt++) {
            int r = m0 + wm + mt * 16 + gid;
            int c = n0 + wn + nt * 8 + 2 * tig;
            *(float2*)&C[(size_t)r * DDIM + c] = make_float2(acc[mt][nt][0], acc[mt][nt][1]);
            *(float2*)&C[(size_t)(r + 8) * DDIM + c] = make_float2(acc[mt][nt][2], acc[mt][nt][3]);
        }
}

// corr: 128x64 tiles, grid (4,2,32) = 256 blocks
__global__ __launch_bounds__(256, 2) void k_corr(const float* __restrict__ x,
                                                 const float* __restrict__ sc,
                                                 float* __restrict__ Ablk) {
    __shared__ __align__(16) float sm[SMEM_FLOATS_64];
    const int m0 = blockIdx.y * 128, n0 = blockIdx.x * 64, b = blockIdx.z;
    const float* base = x + (size_t)b * NPG * DDIM;
    float acc[2][4][4];
    #pragma unroll
    for (int i = 0; i < 2; i++)
        #pragma unroll
        for (int j = 0; j < 4; j++)
            #pragma unroll
            for (int q = 0; q < 4; q++) acc[i][j][q] = 0.f;
    mma_loop64<true>(base + (size_t)m0 * DDIM, DDIM,
                     base + (size_t)n0 * DDIM, DDIM, sm, acc);
    const int lane = threadIdx.x & 31, warp = threadIdx.x >> 5;
    const int gid = lane >> 2, tig = lane & 3;
    const int wm = (warp & 3) * 32, wn = (warp >> 2) * 32;
    const float* scb = sc + b * NPG;
    #pragma unroll
    for (int mt = 0; mt < 2; mt++)
        #pragma unroll
        for (int nt = 0; nt < 4; nt++) {
            int li = m0 + wm + mt * 16 + gid;
            int lj = n0 + wn + nt * 8 + 2 * tig;
            float s0 = scb[li], s1 = scb[li + 8];
            float c0 = scb[lj], c1 = scb[lj + 1];
            float* row0 = Ablk + ((size_t)b * NPG + li) * NPG;
            float* row1 = Ablk + ((size_t)b * NPG + li + 8) * NPG;
            *(float2*)&row0[lj] = make_float2(acc[mt][nt][0] * s0 * c0, acc[mt][nt][1] * s0 * c1);
            *(float2*)&row1[lj] = make_float2(acc[mt][nt][2] * s1 * c0, acc[mt][nt][3] * s1 * c1);
        }
}

// aggr partials: 128x128 tiles, grid (2,2,96) = 384 blocks
__global__ __launch_bounds__(256, 2) void k_aggr_part(const float* __restrict__ Adj,
                                                      const float* __restrict__ G,
                                                      float* __restrict__ P) {
    __shared__ __align__(16) float sm[SMEM_FLOATS_128];
    const int m0 = blockIdx.y * 128, n0 = blockIdx.x * 128;
    const int z = blockIdx.z, b = z & 31, t = z >> 5;
    float acc[2][8][4];
    #pragma unroll
    for (int i = 0; i < 2; i++)
        #pragma unroll
        for (int j = 0; j < 8; j++)
            #pragma unroll
            for (int q = 0; q < 4; q++) acc[i][j][q] = 0.f;
    const float* Ag = Adj + ((size_t)(t * BGRP + b)) * NPG * NPG + (size_t)m0 * NPG;
    const float* Bg = G + (size_t)t * PLANE_H + (size_t)b * NPG * DDIM + n0;
    mma_loop128<false>(Ag, NPG, Bg, DDIM, sm, acc);
    float* Pp = P + (size_t)t * PLANE_H + (size_t)b * NPG * DDIM;
    const int lane = threadIdx.x & 31, warp = threadIdx.x >> 5;
    const int gid = lane >> 2, tig = lane & 3;
    const int wm = (warp & 3) * 32, wn = (warp >> 2) * 64;
    #pragma unroll
    for (int mt = 0; mt < 2; mt++)
        #pragma unroll
        for (int nt = 0; nt < 8; nt++) {
            int r = m0 + wm + mt * 16 + gid;
            int c = n0 + wn + nt * 8 + 2 * tig;
            *(float2*)&Pp[(size_t)r * DDIM + c] = make_float2(acc[mt][nt][0], acc[mt][nt][1]);
            *(float2*)&Pp[(size_t)(r + 8) * DDIM + c] = make_float2(acc[mt][nt][2], acc[mt][nt][3]);
        }
}

__global__ void k_red(const float* __restrict__ P, const float* __restrict__ bgl,
                      float* __restrict__ H) {
    int i = blockIdx.x * blockDim.x + threadIdx.x;
    if (i >= PLANE_H) return;
    int c = i & 255;
    float bias = bgl[c] + bgl[DDIM + c] + bgl[2 * DDIM + c];
    float v = P[i] + P[i + PLANE_H] + P[i + 2 * PLANE_H] + bias;
    H[i] = fmaxf(v, 0.f);
}

// ahat: 128x64 tiles, grid (4,2,32) = 256 blocks
__global__ __launch_bounds__(256, 2) void k_ahat(const float* __restrict__ HT,
                                                 const float* __restrict__ Hn,
                                                 float* __restrict__ Ablk) {
    __shared__ __align__(16) float sm[SMEM_FLOATS_64];
    const int m0 = blockIdx.y * 128, n0 = blockIdx.x * 64, b = blockIdx.z;
    float acc[2][4][4];
    #pragma unroll
    for (int i = 0; i < 2; i++)
        #pragma unroll
        for (int j = 0; j < 4; j++)
            #pragma unroll
            for (int q = 0; q < 4; q++) acc[i][j][q] = 0.f;
    mma_loop64<true>(HT + ((size_t)b * NPG + m0) * DDIM, DDIM,
                     Hn + ((size_t)b * NPG + n0) * DDIM, DDIM, sm, acc);
    const int lane = threadIdx.x & 31, warp = threadIdx.x >> 5;
    const int gid = lane >> 2, tig = lane & 3;
    const int wm = (warp & 3) * 32, wn = (warp >> 2) * 32;
    #pragma unroll
    for (int mt = 0; mt < 2; mt++)
        #pragma unroll
        for (int nt = 0; nt < 4; nt++) {
            int li = m0 + wm + mt * 16 + gid;
            int lj = n0 + wn + nt * 8 + 2 * tig;
            float* row0 = Ablk + ((size_t)b * NPG + li) * NPG;
            float* row1 = Ablk + ((size_t)b * NPG + li + 8) * NPG;
            float2 o0 = *(const float2*)&row0[lj];
            float2 o1 = *(const float2*)&row1[lj];
            float2 v0, v1;
            v0.x = 0.5f * o0.x + 0.5f / (1.0f + expf(-acc[mt][nt][0]));
            v0.y = 0.5f * o0.y + 0.5f / (1.0f + expf(-acc[mt][nt][1]));
            v1.x = 0.5f * o1.x + 0.5f / (1.0f + expf(-acc[mt][nt][2]));
            v1.y = 0.5f * o1.y + 0.5f / (1.0f + expf(-acc[mt][nt][3]));
            *(float2*)&row0[lj] = v0;
            *(float2*)&row1[lj] = v1;
        }
}

// ---------------- small kernels ---------------------------------------------
__global__ void k_mask_detect(const unsigned char* __restrict__ em,
                              const unsigned char* __restrict__ pm) {
    __shared__ int nz[4];
    if (threadIdx.x < 4) nz[threadIdx.x] = 0;
    __syncthreads();
    int loc[4] = {0, 0, 0, 0};
    for (int i = threadIdx.x; i < NMASK; i += 256) {
        if (em[i]) loc[i & 3]++;
        if (pm[i]) loc[i & 3]++;
    }
    #pragma unroll
    for (int j = 0; j < 4; j++) if (loc[j]) atomicAdd(&nz[j], loc[j]);
    __syncthreads();
    if (threadIdx.x == 0) {
        int mode;
        if (nz[1] > 0) mode = 0;
        else if (nz[0] > 0) mode = 1;
        else mode = 2;
        g_mask_mode = mode;
    }
}

__global__ void k_mask_decode(const unsigned char* __restrict__ em,
                              const unsigned char* __restrict__ pm,
                              float* __restrict__ emf, float* __restrict__ pmf) {
    int i = blockIdx.x * blockDim.x + threadIdx.x;
    if (i >= NMASK) return;
    int mode = g_mask_mode;
    float e, p;
    if (mode == 0) { e = em[i] ? 1.f : 0.f; p = pm[i] ? 1.f : 0.f; }
    else if (mode == 1) { e = ((const int*)em)[i] ? 1.f : 0.f; p = ((const int*)pm)[i] ? 1.f : 0.f; }
    else { e = (((const float*)em)[i] != 0.f) ? 1.f : 0.f; p = (((const float*)pm)[i] != 0.f) ? 1.f : 0.f; }
    emf[i] = e; pmf[i] = p;
}

__global__ void k_rownorm(const float* __restrict__ x, float* __restrict__ nrm,
                          float* __restrict__ rinv) {
    int warp = (blockIdx.x * blockDim.x + threadIdx.x) >> 5;
    int lane = threadIdx.x & 31;
    if (warp >= NNODE) return;
    const float* r = x + (size_t)warp * DDIM;
    float s = 0.f;
    for (int j = lane; j < DDIM; j += 32) { float v = r[j]; s += v * v; }
    #pragma unroll
    for (int o = 16; o; o >>= 1) s += __shfl_xor_sync(0xffffffffu, s, o);
    if (!lane) { float n = sqrtf(s); nrm[warp] = n; rinv[warp] = 1.0f / n; }
}

__global__ void k_colsum(const float* __restrict__ x, const float* __restrict__ rinv,
                         float* __restrict__ svec) {
    int d = threadIdx.x;
    int r0 = blockIdx.x * 32;
    float acc = 0.f;
    for (int r = r0; r < r0 + 32; r++)
        acc += x[(size_t)r * DDIM + d] * rinv[r];
    atomicAdd(&svec[d], acc);
}

__global__ void k_scale(const float* __restrict__ x, const float* __restrict__ rinv,
                        const float* __restrict__ svec, float* __restrict__ sc) {
    int warp = (blockIdx.x * blockDim.x + threadIdx.x) >> 5;
    int lane = threadIdx.x & 31;
    if (warp >= NNODE) return;
    const float* r = x + (size_t)warp * DDIM;
    float dot = 0.f;
    for (int j = lane; j < DDIM; j += 32) dot += r[j] * svec[j];
    #pragma unroll
    for (int o = 16; o; o >>= 1) dot += __shfl_xor_sync(0xffffffffu, dot, o);
    if (!lane) {
        float rowsum = dot * rinv[warp];
        sc[warp] = rsqrtf(fabsf(rowsum) + ZERO_EPS) * rinv[warp];
    }
}

__global__ void k_scatter_w(const int* __restrict__ ei, const float* __restrict__ ew,
                            float* __restrict__ Adj) {
    int e = blockIdx.x * blockDim.x + threadIdx.x;
    if (e >= NEDGE) return;
    int src = ei[e], dst = ei[NEDGE + e];
    int b = src >> 8, sl = src & 255, dl = dst & 255;
    atomicAdd(&Adj[(((size_t)b << 8) + dl) * NPG + sl], ew[e]);
}

__global__ void k_scatter_A(const int* __restrict__ ei, const float* __restrict__ Ablk,
                            float* __restrict__ Adj) {
    int e = blockIdx.x * blockDim.x + threadIdx.x;
    if (e >= NEDGE) return;
    int src = ei[e], dst = ei[NEDGE + e];
    int b = src >> 8, sl = src & 255, dl = dst & 255;
    float w = Ablk[(((size_t)b << 8) + sl) * NPG + dl];
    atomicAdd(&Adj[(((size_t)b << 8) + dl) * NPG + sl], w);
}

// ---------------- final maps ------------------------------------------------
__global__ __launch_bounds__(256) void k_final(const float* __restrict__ Ablk,
                                               const float* __restrict__ emf,
                                               const float* __restrict__ pmf,
                                               float* __restrict__ out) {
    int b = blockIdx.x;
    __shared__ float ems[NPG], pms[NPG];
    __shared__ float me[NPG], mp[NPG];
    __shared__ float red[256];
    int t = threadIdx.x;
    ems[t] = emf[b * NPG + t];
    pms[t] = pmf[b * NPG + t];
    __syncthreads();
    int warp = t >> 5, lane = t & 31;
    for (int r = warp; r < NPG; r += 8) {
        const float* row = Ablk + ((size_t)b * NPG + r) * NPG;
        float s = 0.f, es = 0.f, ps = 0.f;
        for (int j = lane; j < NPG; j += 32) {
            float a = row[j];
            s += a; es += a * ems[j]; ps += a * pms[j];
        }
        #pragma unroll
        for (int o = 16; o; o >>= 1) {
            s  += __shfl_xor_sync(0xffffffffu, s, o);
            es += __shfl_xor_sync(0xffffffffu, es, o);
            ps += __shfl_xor_sync(0xffffffffu, ps, o);
        }
        if (!lane) { me[r] = s - ps; mp[r] = s - es; }
    }
    __syncthreads();
    for (int pass = 0; pass < 2; pass++) {
        float v = pass ? mp[t] : me[t];
        red[t] = v; __syncthreads();
        for (int s2 = 128; s2; s2 >>= 1) {
            if (t < s2) red[t] = fminf(red[t], red[t + s2]);
            __syncthreads();
        }
        float mn = red[0]; __syncthreads();
        red[t] = v; __syncthreads();
        for (int s2 = 128; s2; s2 >>= 1) {
            if (t < s2) red[t] = fmaxf(red[t], red[t + s2]);
            __syncthreads();
        }
        float mx = red[0]; __syncthreads();
        float u = (v - mn) / (mx - mn + ZERO_EPS);
        red[t] = u; __syncthreads();
        for (int s2 = 128; s2; s2 >>= 1) {
            if (t < s2) red[t] += red[t + s2];
            __syncthreads();
        }
        float sm = red[0]; __syncthreads();
        out[pass * (BGRP * NPG) + b * NPG + t] = u / (sm + ZERO_EPS);
    }
}

// ---------------- host ------------------------------------------------------
extern "C" void kernel_launch(void* const* d_in, const int* in_sizes, int n_in,
                              void* d_out, int out_size) {
    const float*     x    = (const float*)d_in[0];
    const int*       ei_e = (const int*)d_in[1];
    const float*     ew_e = (const float*)d_in[2];
    const int*       ei_p = (const int*)d_in[3];
    const float*     ew_p = (const float*)d_in[4];
    const int*       ei_o = (const int*)d_in[5];
    const float*     ew_o = (const float*)d_in[6];
    const unsigned char* em = (const unsigned char*)d_in[7];
    const unsigned char* pm = (const unsigned char*)d_in[8];
    const float*     Wg   = (const float*)d_in[9];
    const float*     bg   = (const float*)d_in[10];
    const float*     Td   = (const float*)d_in[11];
    float* out = (float*)d_out;

    float *H0, *H1, *G, *P, *HT, *Ablk, *Adj, *nrm, *rinv, *sc, *svec, *emf, *pmf;
    cudaGetSymbolAddress((void**)&H0,   g_H0);
    cudaGetSymbolAddress((void**)&H1,   g_H1);
    cudaGetSymbolAddress((void**)&G,    g_G);
    cudaGetSymbolAddress((void**)&P,    g_P);
    cudaGetSymbolAddress((void**)&HT,   g_HT);
    cudaGetSymbolAddress((void**)&Ablk, g_Ablk);
    cudaGetSymbolAddress((void**)&Adj,  g_Adj);
    cudaGetSymbolAddress((void**)&nrm,  g_nrm);
    cudaGetSymbolAddress((void**)&rinv, g_rinv);
    cudaGetSymbolAddress((void**)&sc,   g_sc);
    cudaGetSymbolAddress((void**)&svec, g_svec);
    cudaGetSymbolAddress((void**)&emf,  g_emf);
    cudaGetSymbolAddress((void**)&pmf,  g_pmf);

    static cudaStream_t s1 = nullptr;
    static cudaEvent_t evR, evAdj, evCorr, evH0, evG1;
    if (!s1) {
        cudaStreamCreateWithFlags(&s1, cudaStreamNonBlocking);
        cudaEventCreateWithFlags(&evR,    cudaEventDisableTiming);
        cudaEventCreateWithFlags(&evAdj,  cudaEventDisableTiming);
        cudaEventCreateWithFlags(&evCorr, cudaEventDisableTiming);
        cudaEventCreateWithFlags(&evH0,   cudaEventDisableTiming);
        cudaEventCreateWithFlags(&evG1,   cudaEventDisableTiming);
    }

    const size_t ADJ1 = (size_t)BGRP * NPG * NPG;

    // ---- fork side stream ----
    cudaEventRecord(evR, 0);
    cudaStreamWaitEvent(s1, evR, 0);

    // ---- side stream: masks, normalization chain, L0 adjacency, corr ----
    k_mask_detect<<<1, 256, 0, s1>>>(em, pm);
    k_mask_decode<<<NMASK / 256, 256, 0, s1>>>(em, pm, emf, pmf);
    cudaMemsetAsync(svec, 0, DDIM * sizeof(float), s1);
    k_rownorm<<<NNODE / 8, 256, 0, s1>>>(x, nrm, rinv);
    k_colsum<<<256, 256, 0, s1>>>(x, rinv, svec);
    k_scale<<<NNODE / 8, 256, 0, s1>>>(x, rinv, svec, sc);
    cudaMemsetAsync(Adj, 0, 3 * ADJ1 * sizeof(float), s1);
    k_scatter_w<<<NEDGE / 256, 256, 0, s1>>>(ei_e, ew_e, Adj);
    k_scatter_w<<<NEDGE / 256, 256, 0, s1>>>(ei_p, ew_p, Adj + ADJ1);
    k_scatter_w<<<NEDGE / 256, 256, 0, s1>>>(ei_o, ew_o, Adj + 2 * ADJ1);
    cudaEventRecord(evAdj, s1);
    k_corr<<<dim3(4, 2, BGRP), 256, 0, s1>>>(x, sc, Ablk);
    cudaEventRecord(evCorr, s1);

    // ---- main: layer-0 feature GEMM ----
    k_gemm_nn<<<dim3(2, 64, 3), 256>>>(x, Wg, G);
    cudaStreamWaitEvent(0, evAdj, 0);
    k_aggr_part<<<dim3(2, 2, 96), 256>>>(Adj, G, P);
    k_red<<<PLANE_H / 256, 256>>>(P, bg, H0);
    cudaEventRecord(evH0, 0);

    // ---- side stream: layer-1 feature GEMM overlapped with L0 epilogue ----
    cudaStreamWaitEvent(s1, evH0, 0);
    k_gemm_nn<<<dim3(2, 64, 3), 256, 0, s1>>>(H0, Wg + 3 * DDIM * DDIM, G);
    cudaEventRecord(evG1, s1);

    // ---- main: HT, ahat L0, layer-1 adjacency ----
    k_gemm_ht<<<dim3(4, 64, 1), 256>>>(H0, Td, HT);
    cudaStreamWaitEvent(0, evCorr, 0);
    k_ahat<<<dim3(4, 2, BGRP), 256>>>(HT, H0, Ablk);
    cudaMemsetAsync(Adj, 0, 3 * ADJ1 * sizeof(float));
    k_scatter_A<<<NEDGE / 256, 256>>>(ei_e, Ablk, Adj);
    k_scatter_A<<<NEDGE / 256, 256>>>(ei_p, Ablk, Adj + ADJ1);
    k_scatter_A<<<NEDGE / 256, 256>>>(ei_o, Ablk, Adj + 2 * ADJ1);

    // ---- main: layer 1 (join side stream's G) ----
    cudaStreamWaitEvent(0, evG1, 0);
    k_aggr_part<<<dim3(2, 2, 96), 256>>>(Adj, G, P);
    k_red<<<PLANE_H / 256, 256>>>(P, bg + 3 * DDIM, H1);
    k_gemm_ht<<<dim3(4, 64, 1), 256>>>(H1, Td + DDIM * DDIM, HT);
    k_ahat<<<dim3(4, 2, BGRP), 256>>>(HT, H1, Ablk);

    // ---- final maps ----
    k_final<<<BGRP, 256>>>(Ablk, emf, pmf, out);
}